// round 1
// baseline (speedup 1.0000x reference)
#include <cuda_runtime.h>

#define IMG_H 1080
#define IMG_W 1920
#define PLANE (IMG_H * IMG_W)

// JPEG-style base quant table (row-major 8x8)
__constant__ float c_qbase[64] = {
    16, 11, 10, 16, 24, 40, 51, 61,
    12, 12, 14, 19, 26, 58, 60, 55,
    14, 13, 16, 24, 40, 57, 69, 56,
    14, 17, 22, 29, 51, 87, 80, 62,
    18, 22, 37, 56, 68, 109, 103, 77,
    24, 35, 55, 64, 81, 104, 113, 92,
    49, 64, 78, 87, 103, 121, 120, 101,
    72, 92, 95, 98, 112, 100, 103, 99
};

__global__ __launch_bounds__(1024)
void h264_dct_kernel(const float* __restrict__ x, float* __restrict__ out) {
    // CTA covers an 8-row x 128-col strip = 16 8x8 blocks. One thread per pixel.
    __shared__ float sA[8][128];
    __shared__ float sB[8][128];
    __shared__ float sBas[8][8];   // sBas[k][n]  = basis[k][n]
    __shared__ float sBasT[8][8];  // sBasT[n][k] = basis[k][n]
    __shared__ float sQ[8][8];     // scaled quant matrix

    const int tx  = threadIdx.x;          // 0..127 (column within strip)
    const int ty  = threadIdx.y;          // 0..7   (row within strip)
    const int tid = ty * 128 + tx;

    if (tid < 64) {
        int k = tid >> 3, n = tid & 7;
        float v = (k == 0) ? 0.35355339059327373f
                           : 0.5f * cospif((float)(k * (2 * n + 1)) * (1.0f / 16.0f));
        sBas[k][n]  = v;
        sBasT[n][k] = v;
        // QF=28 >= 25 -> scale = 200 - 2*28 = 144 ; q = max(base*144/50, 1)
        float q = c_qbase[tid] * 2.88f;
        sQ[k][n] = fmaxf(q, 1.0f);
    }

    const int col = blockIdx.x * 128 + tx;
    const int row = blockIdx.y * 8 + ty;
    const int bat = blockIdx.z;

    const size_t base = (size_t)bat * (3 * (size_t)PLANE) + (size_t)row * IMG_W + col;

    // Load BGR once, keep in registers for the epilogue.
    const float vb = x[base];
    const float vg = x[base + PLANE];
    const float vr = x[base + 2 * PLANE];
    const float yv = 0.114f * vb + 0.587f * vg + 0.299f * vr;

    sA[ty][tx] = yv;
    __syncthreads();

    // Stage 1: vertical DCT  t[k][j] = sum_i basis[k][i] * y[i][j]
    {
        float acc = 0.0f;
        #pragma unroll
        for (int i = 0; i < 8; ++i)
            acc = fmaf(sBas[ty][i], sA[i][tx], acc);   // sBas[ty][i] uniform per warp
        sB[ty][tx] = acc;
    }
    __syncthreads();

    const int l   = tx & 7;        // column within 8x8 block
    const int bx8 = tx & ~7;       // block base column

    // Stage 2: horizontal DCT + quantize
    // coef[k][l] = sum_j t[k][j] * basis[l][j] ; then round-half-even quant
    {
        float coef = 0.0f;
        #pragma unroll
        for (int j = 0; j < 8; ++j)
            coef = fmaf(sB[ty][bx8 + j], sBasT[j][l], coef);
        float q  = sQ[ty][l];
        float cq = rintf(coef / (q + 1e-8f)) * q;      // matches jnp.round (half-to-even)
        __syncthreads();                                // all stage-2 reads of sB done
        sA[ty][tx] = cq;
    }
    __syncthreads();

    // Stage 3: vertical IDCT  u[a][j] = sum_i basis[i][a] * coefq[i][j]
    {
        float acc = 0.0f;
        #pragma unroll
        for (int i = 0; i < 8; ++i)
            acc = fmaf(sBasT[ty][i], sA[i][tx], acc);  // sBasT[ty][i] uniform per warp
        sB[ty][tx] = acc;
    }
    __syncthreads();

    // Stage 4: horizontal IDCT + epilogue
    // rec[a][b] = sum_j u[a][j] * basis[j][b]
    {
        float rec = 0.0f;
        #pragma unroll
        for (int j = 0; j < 8; ++j)
            rec = fmaf(sB[ty][bx8 + j], sBas[j][l], rec);

        const float yd = rec - yv;
        float ob = fminf(fmaxf(vb + 0.114f * yd, 0.0f), 255.0f);
        float og = fminf(fmaxf(vg + 0.587f * yd, 0.0f), 255.0f);
        float orr = fminf(fmaxf(vr + 0.299f * yd, 0.0f), 255.0f);

        out[base]             = ob;
        out[base + PLANE]     = og;
        out[base + 2 * PLANE] = orr;
    }
}

extern "C" void kernel_launch(void* const* d_in, const int* in_sizes, int n_in,
                              void* d_out, int out_size) {
    const float* x = (const float*)d_in[0];
    float* out = (float*)d_out;

    // x: (B, 3, 1080, 1920). Derive B from element count.
    int B = in_sizes[0] / (3 * PLANE);

    dim3 block(128, 8, 1);
    dim3 grid(IMG_W / 128, IMG_H / 8, B);   // 15 x 135 x B
    h264_dct_kernel<<<grid, block>>>(x, out);
}

// round 2
// speedup vs baseline: 2.4879x; 2.4879x over previous
#include <cuda_runtime.h>

#define IMG_H 1080
#define IMG_W 1920
#define PLANE (IMG_H * IMG_W)

// JPEG-style base quant table (row-major 8x8)
__constant__ float c_qbase[64] = {
    16, 11, 10, 16, 24, 40, 51, 61,
    12, 12, 14, 19, 26, 58, 60, 55,
    14, 13, 16, 24, 40, 57, 69, 56,
    14, 17, 22, 29, 51, 87, 80, 62,
    18, 22, 37, 56, 68, 109, 103, 77,
    24, 35, 55, 64, 81, 104, 113, 92,
    49, 64, 78, 87, 103, 121, 120, 101,
    72, 92, 95, 98, 112, 100, 103, 99
};

// DCT-II basis as compile-time constants -> FFMA with immediate operands
#define H1 0.4903926402016152f
#define H2 0.4619397662556434f
#define H3 0.4157348061512726f
#define H4 0.3535533905932738f
#define H5 0.2777851165098011f
#define H6 0.1913417161825449f
#define H7 0.0975451610080641f

__device__ constexpr float BAS[8][8] = {
    { H4,  H4,  H4,  H4,  H4,  H4,  H4,  H4},
    { H1,  H3,  H5,  H7, -H7, -H5, -H3, -H1},
    { H2,  H6, -H6, -H2, -H2, -H6,  H6,  H2},
    { H3, -H7, -H1, -H5,  H5,  H1,  H7, -H3},
    { H4, -H4, -H4,  H4,  H4, -H4, -H4,  H4},
    { H5, -H1,  H7,  H3, -H3, -H7,  H1, -H5},
    { H6, -H2,  H2, -H6, -H6,  H2, -H2,  H6},
    { H7, -H5,  H3, -H1,  H1, -H3,  H5, -H7}
};

__global__ __launch_bounds__(128)
void h264_dct_kernel(const float* __restrict__ x, float* __restrict__ out) {
    // CTA: 128 threads. Thread t owns the 8-pixel column (rows rb..rb+7) at
    // global column blockIdx.x*128 + t. All 8-pt transforms are in registers
    // with immediate basis constants; smem is only used for two 8x8 transposes.
    __shared__ float s[8][129];   // pad 129 -> bank = (row + col) % 32, conflict-free
    __shared__ float sQ[8][9];    // pad 9   -> conflict-free quant-table reads

    const int t = threadIdx.x;
    if (t < 64) {
        int k = t >> 3, u = t & 7;
        // QF=28 >= 25 -> scale = 144 ; q = max(base*144/50, 1) (exact fp32 division)
        sQ[k][u] = fmaxf((c_qbase[t] * 144.0f) / 50.0f, 1.0f);
    }

    const int g = t >> 3;         // 8x8 block index within the strip
    const int l = t & 7;          // lane within the block
    const int col = blockIdx.x * 128 + t;
    const int r0  = blockIdx.y * 8;
    const size_t base = (size_t)blockIdx.z * (3 * (size_t)PLANE)
                      + (size_t)r0 * IMG_W + col;

    float vb[8], vg[8], vr[8], a[8], w[8];

    // Load BGR (each global byte read exactly once), form luma column.
    #pragma unroll
    for (int i = 0; i < 8; ++i) {
        size_t p = base + (size_t)i * IMG_W;
        vb[i] = x[p];
        vg[i] = x[p + PLANE];
        vr[i] = x[p + 2 * PLANE];
        a[i]  = 0.114f * vb[i] + 0.587f * vg[i] + 0.299f * vr[i];
    }

    // Vertical DCT (registers): w[k] = sum_i BAS[k][i] * y[i]
    #pragma unroll
    for (int k = 0; k < 8; ++k) {
        float acc = 0.0f;
        #pragma unroll
        for (int i = 0; i < 8; ++i) acc = fmaf(BAS[k][i], a[i], acc);
        w[k] = acc;
    }

    // Transpose 1: thread -> owns row l of block g
    #pragma unroll
    for (int k = 0; k < 8; ++k) s[k][t] = w[k];
    __syncthreads();
    #pragma unroll
    for (int j = 0; j < 8; ++j) a[j] = s[l][(g << 3) + j];
    __syncthreads();   // all reads done before buffer reuse

    // Horizontal DCT + quantize (round-half-even, exact division) in registers
    float cq[8];
    #pragma unroll
    for (int u = 0; u < 8; ++u) {
        float acc = 0.0f;
        #pragma unroll
        for (int j = 0; j < 8; ++j) acc = fmaf(a[j], BAS[u][j], acc);
        float q = sQ[l][u];
        cq[u] = rintf(acc / (q + 1e-8f)) * q;
    }

    // Horizontal IDCT in registers: w[b] = sum_u cq[u] * BAS[u][b]
    #pragma unroll
    for (int b = 0; b < 8; ++b) {
        float acc = 0.0f;
        #pragma unroll
        for (int u = 0; u < 8; ++u) acc = fmaf(cq[u], BAS[u][b], acc);
        w[b] = acc;
    }

    // Transpose 2: back to column ownership
    #pragma unroll
    for (int b = 0; b < 8; ++b) s[l][(g << 3) + b] = w[b];
    __syncthreads();
    #pragma unroll
    for (int i = 0; i < 8; ++i) a[i] = s[i][t];

    // Vertical IDCT + epilogue (recompute luma from registers, write BGR once)
    #pragma unroll
    for (int ar = 0; ar < 8; ++ar) {
        float rec = 0.0f;
        #pragma unroll
        for (int i = 0; i < 8; ++i) rec = fmaf(BAS[i][ar], a[i], rec);

        float yv = 0.114f * vb[ar] + 0.587f * vg[ar] + 0.299f * vr[ar];
        float yd = rec - yv;

        size_t p = base + (size_t)ar * IMG_W;
        out[p]             = fminf(fmaxf(vb[ar] + 0.114f * yd, 0.0f), 255.0f);
        out[p + PLANE]     = fminf(fmaxf(vg[ar] + 0.587f * yd, 0.0f), 255.0f);
        out[p + 2 * PLANE] = fminf(fmaxf(vr[ar] + 0.299f * yd, 0.0f), 255.0f);
    }
}

extern "C" void kernel_launch(void* const* d_in, const int* in_sizes, int n_in,
                              void* d_out, int out_size) {
    const float* x = (const float*)d_in[0];
    float* out = (float*)d_out;

    int B = in_sizes[0] / (3 * PLANE);

    dim3 block(128, 1, 1);
    dim3 grid(IMG_W / 128, IMG_H / 8, B);   // 15 x 135 x B
    h264_dct_kernel<<<grid, block>>>(x, out);
}